// round 15
// baseline (speedup 1.0000x reference)
#include <cuda_runtime.h>
#include <cuda_fp16.h>
#include <math.h>
#include <stdint.h>

// ---------------- problem constants ----------------
#define BN    2
#define SQL   1024
#define DIM   2048
#define NH    16
#define HD    128
#define SP    1024
#define SS    1024
#define SMm   512
#define SKV   2560
#define DP    1280
#define DS    1024
#define DMm   768
#define INNER 8192

typedef __half fp16;

// ---------------- scratch ----------------
__device__ __align__(256) float g_h  [BN*SQL*DIM];

__device__ __align__(256) fp16 g_xn [BN*SQL*DIM];
__device__ __align__(256) fp16 g_pk [BN*SP*DP];
__device__ __align__(256) fp16 g_sk [BN*SS*DS];
__device__ __align__(256) fp16 g_mk [BN*SMm*DMm];
__device__ __align__(256) fp16 g_ct [BN*SQL*DIM];
__device__ __align__(256) fp16 g_ln [BN*SQL*DIM];
__device__ __align__(256) fp16 g_md [BN*SQL*INNER];

__device__ __align__(256) fp16 g_q  [BN*SQL*DIM];
__device__ __align__(256) fp16 g_k1 [BN*SKV*DIM];
__device__ __align__(256) fp16 g_v1 [BN*SKV*DIM];

__device__ __align__(256) fp16 g_wq [DIM*DIM];
__device__ __align__(256) fp16 g_kp [DIM*DP];
__device__ __align__(256) fp16 g_vp [DIM*DP];
__device__ __align__(256) fp16 g_ks [DIM*DS];
__device__ __align__(256) fp16 g_vs [DIM*DS];
__device__ __align__(256) fp16 g_km [DIM*DMm];
__device__ __align__(256) fp16 g_vm [DIM*DMm];
__device__ __align__(256) fp16 g_wo [DIM*DIM];
__device__ __align__(256) fp16 g_w1 [INNER*DIM];
__device__ __align__(256) fp16 g_w2 [DIM*INNER];

// ---------------- helpers ----------------
#define CP16(dst, src) asm volatile("cp.async.cg.shared.global [%0], [%1], 16;" :: "r"(dst), "l"(src))
#define CP4(dst, src)  asm volatile("cp.async.ca.shared.global [%0], [%1], 4;"  :: "r"(dst), "l"(src))
#define CP_COMMIT()  asm volatile("cp.async.commit_group;" ::: "memory")
#define CP_WAIT(n)   asm volatile("cp.async.wait_group %0;" :: "n"(n) : "memory")

__device__ __forceinline__ uint32_t smem_u32(const void* p) {
    uint32_t a;
    asm("{ .reg .u64 t; cvta.to.shared.u64 t, %1; cvt.u32.u64 %0, t; }" : "=r"(a) : "l"(p));
    return a;
}
__device__ __forceinline__ void mma_f16(float* c, const uint32_t* a, const uint32_t* b) {
    asm volatile("mma.sync.aligned.m16n8k16.row.col.f32.f16.f16.f32 "
        "{%0,%1,%2,%3}, {%4,%5,%6,%7}, {%8,%9}, {%0,%1,%2,%3};"
        : "+f"(c[0]), "+f"(c[1]), "+f"(c[2]), "+f"(c[3])
        : "r"(a[0]), "r"(a[1]), "r"(a[2]), "r"(a[3]), "r"(b[0]), "r"(b[1]));
}
__device__ __forceinline__ void ldmx4(uint32_t* r, uint32_t addr) {
    asm volatile("ldmatrix.sync.aligned.m8n8.x4.shared.b16 {%0,%1,%2,%3}, [%4];"
        : "=r"(r[0]), "=r"(r[1]), "=r"(r[2]), "=r"(r[3]) : "r"(addr));
}
__device__ __forceinline__ void ldmx4t(uint32_t* r, uint32_t addr) {
    asm volatile("ldmatrix.sync.aligned.m8n8.x4.trans.shared.b16 {%0,%1,%2,%3}, [%4];"
        : "=r"(r[0]), "=r"(r[1]), "=r"(r[2]), "=r"(r[3]) : "r"(addr));
}
__device__ __forceinline__ uint32_t pack2(fp16 a, fp16 b) {
    __half2 t(a, b);
    return *(uint32_t*)&t;
}

// ---------------- prep kernels ----------------
__global__ __launch_bounds__(256) void cvt_all(
    const float* __restrict__ x0, fp16* __restrict__ y0, int c0,
    const float* __restrict__ x1, fp16* __restrict__ y1, int c1,
    const float* __restrict__ x2, fp16* __restrict__ y2, int c2)
{
    int b = blockIdx.x;
    const float* x; fp16* y; int base;
    if (b < c0)      { x = x0; y = y0; base = b; }
    else if (b < c1) { x = x1; y = y1; base = b - c0; }
    else             { x = x2; y = y2; base = b - c1; }
    size_t i = ((size_t)base * 256 + threadIdx.x) * 4;
    float4 v = *(const float4*)(x + i);
    uint2 o;
    o.x = pack2(__float2half_rn(v.x), __float2half_rn(v.y));
    o.y = pack2(__float2half_rn(v.z), __float2half_rn(v.w));
    *(uint2*)(y + i) = o;
}

struct WEnt { const float* W; fp16* O; int K; int N; int cum; };
struct WTab { WEnt e[10]; };

__global__ __launch_bounds__(256) void tcvt_all(WTab tab) {
    __shared__ float t[32][33];
    int lin = blockIdx.x;
    int s = 0;
#pragma unroll
    for (int i = 1; i < 10; i++) if (lin >= tab.e[i].cum) s = i;
    const float* W = tab.e[s].W;
    fp16* O = tab.e[s].O;
    int K = tab.e[s].K, N = tab.e[s].N;
    int local = lin - tab.e[s].cum;
    int nx = N >> 5;
    int n0 = (local % nx) * 32, k0 = (local / nx) * 32;
    int tx = threadIdx.x & 31, ty = threadIdx.x >> 5;
#pragma unroll
    for (int r = 0; r < 32; r += 8)
        t[ty + r][tx] = W[(size_t)(k0 + ty + r) * N + n0 + tx];
    __syncthreads();
#pragma unroll
    for (int r = 0; r < 32; r += 8)
        O[(size_t)(n0 + ty + r) * K + k0 + tx] = __float2half_rn(t[tx][ty + r]);
}

__global__ __launch_bounds__(256) void rms_cvt_kernel(
    const float* __restrict__ x, const float* __restrict__ w, fp16* __restrict__ y) {
    __shared__ float red[256];
    int row = blockIdx.x;
    const float* xr = x + (size_t)row * DIM;
    float ss = 0.f;
    for (int c = threadIdx.x; c < DIM; c += 256) { float v = xr[c]; ss += v * v; }
    red[threadIdx.x] = ss; __syncthreads();
    for (int s = 128; s > 0; s >>= 1) {
        if (threadIdx.x < s) red[threadIdx.x] += red[threadIdx.x + s];
        __syncthreads();
    }
    float inv = rsqrtf(red[0] / (float)DIM + 1e-6f);
    for (int c = threadIdx.x; c < DIM; c += 256)
        y[(size_t)row * DIM + c] = __float2half_rn(xr[c] * inv * w[c]);
}

__global__ __launch_bounds__(256) void ln_cvt_kernel(
    const float* __restrict__ x, const float* __restrict__ g, const float* __restrict__ b,
    fp16* __restrict__ y) {
    __shared__ float r1[256], r2[256];
    int row = blockIdx.x;
    const float* xr = x + (size_t)row * DIM;
    float s1 = 0.f, s2 = 0.f;
    for (int c = threadIdx.x; c < DIM; c += 256) { float v = xr[c]; s1 += v; s2 += v * v; }
    r1[threadIdx.x] = s1; r2[threadIdx.x] = s2; __syncthreads();
    for (int s = 128; s > 0; s >>= 1) {
        if (threadIdx.x < s) { r1[threadIdx.x] += r1[threadIdx.x + s]; r2[threadIdx.x] += r2[threadIdx.x + s]; }
        __syncthreads();
    }
    float mu = r1[0] / (float)DIM;
    float rstd = rsqrtf(r2[0] / (float)DIM - mu * mu + 1e-5f);
    for (int c = threadIdx.x; c < DIM; c += 256)
        y[(size_t)row * DIM + c] = __float2half_rn((xr[c] - mu) * rstd * g[c] + b[c]);
}

// ---------------- shared GEMM mainloop ----------------
// Block tile 256x128, 8 warps (4m x 2n), warp tile 64x64, ktile 32, 5-stage cp.async.
// Smem per stage: A 256x32 (20KB) + B 128x32 (10KB) = 30KB. 1 CTA/SM (128 accum regs).
#define RS     40
#define A_STGB 20480
#define STGB   30720
#define NSTG   5

__device__ __forceinline__ void gemm_main(
    const fp16* __restrict__ Ab, const fp16* __restrict__ Bb, int K,
    float c[4][8][4], char* dsm, int tid, int wm, int wn, int lid)
{
    uint32_t sbase = smem_u32(dsm);

    auto load_stage = [&](int k0, int st) {
        uint32_t base = sbase + (uint32_t)st * STGB;
        // A: 256 rows x 32k = 1024 cp16
#pragma unroll
        for (int j = 0; j < 4; j++) {
            int rem = tid + j * 256;
            int row = rem >> 2, ch = rem & 3;
            CP16(base + (uint32_t)(row * RS * 2 + ch * 16), Ab + (size_t)row * K + k0 + ch * 8);
        }
        // B: 128 rows x 32k = 512 cp16
        uint32_t bb = base + A_STGB;
#pragma unroll
        for (int j = 0; j < 2; j++) {
            int rem = tid + j * 256;
            int row = rem >> 2, ch = rem & 3;
            CP16(bb + (uint32_t)(row * RS * 2 + ch * 16), Bb + (size_t)row * K + k0 + ch * 8);
        }
    };

    const int nt = K >> 5;
    load_stage(0, 0);   CP_COMMIT();
    load_stage(32, 1);  CP_COMMIT();
    load_stage(64, 2);  CP_COMMIT();
    load_stage(96, 3);  CP_COMMIT();

    int st = 0;
    for (int t = 0; t < nt; t++) {
        int rem = nt - 1 - t;
        if (rem >= 3)      { CP_WAIT(3); }
        else if (rem == 2) { CP_WAIT(2); }
        else if (rem == 1) { CP_WAIT(1); }
        else               { CP_WAIT(0); }
        __syncthreads();
        if (t + 4 < nt) {
            int st4 = st + 4; if (st4 >= NSTG) st4 -= NSTG;
            load_stage((t + 4) << 5, st4);
            CP_COMMIT();
        }

        uint32_t A_b = sbase + (uint32_t)st * STGB;
        uint32_t B_b = A_b + A_STGB;

#pragma unroll
        for (int ks = 0; ks < 2; ks++) {
            int ko = ks * 16;
            uint32_t ah[4][4];
#pragma unroll
            for (int mi = 0; mi < 4; mi++) {
                uint32_t aoff = (uint32_t)((wm * 64 + mi * 16 + (lid & 15)) * RS + ko + ((lid >> 4) << 3)) * 2;
                ldmx4(ah[mi], A_b + aoff);
            }
#pragma unroll
            for (int nh2 = 0; nh2 < 2; nh2++) {
                uint32_t b4[2][4];
#pragma unroll
                for (int p = 0; p < 2; p++) {
                    uint32_t brow = (uint32_t)(wn * 64 + nh2 * 32 + p * 16 + (lid & 7) + ((lid >> 4) << 3));
                    uint32_t boff = (brow * RS + ko + (((lid >> 3) & 1) << 3)) * 2;
                    ldmx4(b4[p], B_b + boff);
                }
#pragma unroll
                for (int mi = 0; mi < 4; mi++)
#pragma unroll
                    for (int nj = 0; nj < 4; nj++)
                        mma_f16(c[mi][nh2 * 4 + nj], ah[mi], &b4[nj >> 1][(nj & 1) * 2]);
            }
        }
        if (++st >= NSTG) st = 0;
    }
}

// ---------------- merged projection GEMM ----------------
struct PSeg {
    const fp16* A; const fp16* Bk; const fp16* Bv;
    const float* bk; const float* bv;
    fp16* Ok; fp16* Ov;
    long aStride, cStride;
    int Kdim, nx, nxK, my, cum;
    float scale;
};
struct PTab { PSeg e[4]; };

__global__ __launch_bounds__(256) void gemm_proj(PTab tab) {
    extern __shared__ __align__(128) char dsm[];
    int tid = threadIdx.x, wid = tid >> 5, lid = tid & 31;
    int wm = wid & 3, wn = wid >> 2;

    int bid = blockIdx.x;
    int s = 0;
#pragma unroll
    for (int i = 1; i < 4; i++) if (bid >= tab.e[i].cum) s = i;
    PSeg sg = tab.e[s];
    int local = bid - sg.cum;
    int per = sg.nx * sg.my;
    int z = local / per;
    int rem2 = local - z * per;
    int mb = rem2 / sg.nx;
    int nbk = rem2 - mb * sg.nx;
    int m0 = mb << 8, n0 = nbk << 7;

    const fp16* B; const float* bias; fp16* O;
    if (nbk < sg.nxK) { B = sg.Bk; bias = sg.bk; O = sg.Ok; }
    else { B = sg.Bv; bias = sg.bv; O = sg.Ov; n0 -= sg.nxK << 7; }

    const fp16* A = sg.A + (size_t)z * sg.aStride + (size_t)m0 * sg.Kdim;
    B += (size_t)n0 * sg.Kdim;
    O += (size_t)z * sg.cStride;
    float scale = sg.scale;

    float c[4][8][4];
#pragma unroll
    for (int mi = 0; mi < 4; mi++)
#pragma unroll
        for (int ni = 0; ni < 8; ni++)
#pragma unroll
            for (int r = 0; r < 4; r++) c[mi][ni][r] = 0.f;

    gemm_main(A, B, sg.Kdim, c, dsm, tid, wm, wn, lid);

#pragma unroll
    for (int mi = 0; mi < 4; mi++) {
#pragma unroll
        for (int ni = 0; ni < 8; ni++) {
            int col = n0 + wn * 64 + ni * 8 + (lid & 3) * 2;
            float bcol0 = bias[col], bcol1 = bias[col + 1];
#pragma unroll
            for (int rh = 0; rh < 2; rh++) {
                int m = m0 + wm * 64 + mi * 16 + (lid >> 2) + rh * 8;
                float v0 = c[mi][ni][rh * 2 + 0];
                float v1 = c[mi][ni][rh * 2 + 1];
                size_t o = (size_t)m * DIM + col;
                *(uint32_t*)&O[o] = pack2(__float2half_rn((v0 + bcol0) * scale),
                                          __float2half_rn((v1 + bcol1) * scale));
            }
        }
    }
}

// ---------------- general GEMM ----------------
// epi: 1: C=res+tanh(g)*(acc+bias) | 2: gelu->fp16 | 3: C=res+tanh(g)*acc
__global__ __launch_bounds__(256) void gemm_mma(
    const fp16* __restrict__ A,
    const fp16* __restrict__ B,
    const float* __restrict__ bias,
    const float* __restrict__ res, const float* __restrict__ gate,
    float* __restrict__ C, fp16* __restrict__ O,
    int N, int K, int epi)
{
    extern __shared__ __align__(128) char dsm[];

    int tid = threadIdx.x, wid = tid >> 5, lid = tid & 31;
    int wm = wid & 3, wn = wid >> 2;
    int m0 = blockIdx.y << 8, n0 = blockIdx.x << 7;

    float c[4][8][4];
#pragma unroll
    for (int mi = 0; mi < 4; mi++)
#pragma unroll
        for (int ni = 0; ni < 8; ni++)
#pragma unroll
            for (int r = 0; r < 4; r++) c[mi][ni][r] = 0.f;

    gemm_main(A + (size_t)m0 * K, B + (size_t)n0 * K, K, c, dsm, tid, wm, wn, lid);

    float gv = (epi == 1 || epi == 3) ? tanhf(*gate) : 0.f;
#pragma unroll
    for (int mi = 0; mi < 4; mi++) {
#pragma unroll
        for (int ni = 0; ni < 8; ni++) {
            int col = n0 + wn * 64 + ni * 8 + (lid & 3) * 2;
            float bcol0 = 0.f, bcol1 = 0.f;
            if (epi == 1) { bcol0 = bias[col]; bcol1 = bias[col + 1]; }
#pragma unroll
            for (int rh = 0; rh < 2; rh++) {
                int m = m0 + wm * 64 + mi * 16 + (lid >> 2) + rh * 8;
                float v0 = c[mi][ni][rh * 2 + 0];
                float v1 = c[mi][ni][rh * 2 + 1];
                size_t o = (size_t)m * N + col;
                if (epi == 1) {
                    C[o]     = res[o]     + gv * (v0 + bcol0);
                    C[o + 1] = res[o + 1] + gv * (v1 + bcol1);
                } else if (epi == 2) {
                    float g0 = 0.5f * v0 * (1.f + erff(v0 * 0.70710678118654752f));
                    float g1 = 0.5f * v1 * (1.f + erff(v1 * 0.70710678118654752f));
                    *(uint32_t*)&O[o] = pack2(__float2half_rn(g0), __float2half_rn(g1));
                } else { // epi == 3
                    C[o]     = res[o]     + gv * v0;
                    C[o + 1] = res[o + 1] + gv * v1;
                }
            }
        }
    }
}

// ---------------- tensor-core flash attention (fp16) ----------------
#define AQ 0
#define AK(st) (17408 + (st) * 8704)
#define AV(st) (34816 + (st) * 8704)
#define AMSK_BYTES 104448
#define ATT_SMEM (AMSK_BYTES + 512)
#define NKT (SKV / 64)

__global__ __launch_bounds__(256) void attn_tc(
    const fp16* __restrict__ qv, const fp16* __restrict__ kk, const fp16* __restrict__ vv,
    const float* __restrict__ qmask, const float* __restrict__ pmask,
    const float* __restrict__ smask, const float* __restrict__ mmask,
    fp16* __restrict__ co)
{
    extern __shared__ __align__(128) char dsm[];
    uint32_t sb = smem_u32(dsm);

    int b = blockIdx.z, h = blockIdx.y, q0 = blockIdx.x * 128;
    int tid = threadIdx.x, wid = tid >> 5, lid = tid & 31;
    int wr = wid * 16;

#pragma unroll
    for (int j = 0; j < 8; j++) {
        int rem = tid + j * 256;
        int r = rem >> 4, cch = rem & 15;
        CP16(sb + (uint32_t)(AQ + r * 136 + cch * 8) * 2,
             qv + (size_t)(b * SQL + q0 + r) * DIM + h * HD + cch * 8);
    }

    auto load_stage = [&](int kt, int st) {
#pragma unroll
        for (int grp = 0; grp < 2; grp++) {
            const fp16* base = grp ? vv : kk;
            uint32_t ab = grp ? (uint32_t)AV(st) : (uint32_t)AK(st);
#pragma unroll
            for (int j = 0; j < 4; j++) {
                int rem = tid + j * 256;
                int r = rem >> 4, cch = rem & 15;
                CP16(sb + (ab + (uint32_t)(r * 136 + cch * 8)) * 2,
                     base + (size_t)(b * SKV + kt + r) * DIM + h * HD + cch * 8);
            }
        }
        if (tid < 64) {
            int kidx = kt + tid;
            const float* srcm;
            if (kidx < SP)           srcm = pmask + b * SP + kidx;
            else if (kidx < SP + SS) srcm = smask + b * SS + (kidx - SP);
            else                     srcm = mmask + b * SMm + (kidx - SP - SS);
            CP4(sb + AMSK_BYTES + st * 256 + tid * 4, srcm);
        }
    };

    float qm2[2];
    qm2[0] = qmask[b * SQL + q0 + wr + (lid >> 2)];
    qm2[1] = qmask[b * SQL + q0 + wr + (lid >> 2) + 8];

    float m2[2] = { -1e30f, -1e30f }, l2[2] = { 0.f, 0.f };
    float o[16][4];
#pragma unroll
    for (int ni = 0; ni < 16; ni++)
#pragma unroll
        for (int r = 0; r < 4; r++) o[ni][r] = 0.f;

    load_stage(0, 0);
    CP_COMMIT();

    for (int t = 0; t < NKT; t++) {
        int st = t & 1;
        CP_WAIT(0);
        __syncthreads();
        if (t + 1 < NKT) { load_stage((t + 1) * 64, st ^ 1); CP_COMMIT(); }

        float cs[8][4];
#pragma unroll
        for (int ni = 0; ni < 8; ni++)
#pragma unroll
            for (int r = 0; r < 4; r++) cs[ni][r] = 0.f;

        uint32_t akb = sb + (uint32_t)AK(st) * 2;
#pragma unroll
        for (int ko = 0; ko < 8; ko++) {
            uint32_t aoff = (uint32_t)((wr + (lid & 15)) * 136 + ko * 16 + ((lid >> 4) << 3)) * 2;
            uint32_t aq[4];
            ldmx4(aq, sb + AQ * 2 + aoff);
#pragma unroll
            for (int p = 0; p < 4; p++) {
                uint32_t brow = (uint32_t)(p * 16 + (lid & 7) + ((lid >> 4) << 3));
                uint32_t boff = (brow * 136 + ko * 16 + (((lid >> 3) & 1) << 3)) * 2;
                uint32_t b4[4];
                ldmx4(b4, akb + boff);
#pragma unroll
                for (int half = 0; half < 2; half++)
                    mma_f16(cs[p * 2 + half], aq, &b4[half * 2]);
            }
        }

        const float* kmf = (const float*)(dsm + AMSK_BYTES + st * 256);
#pragma unroll
        for (int ni = 0; ni < 8; ni++) {
            int c0 = ni * 8 + (lid & 3) * 2;
            float km0 = kmf[c0], km1 = kmf[c0 + 1];
            if (qm2[0] == 0.f || km0 == 0.f) cs[ni][0] = -1e30f;
            if (qm2[0] == 0.f || km1 == 0.f) cs[ni][1] = -1e30f;
            if (qm2[1] == 0.f || km0 == 0.f) cs[ni][2] = -1e30f;
            if (qm2[1] == 0.f || km1 == 0.f) cs[ni][3] = -1e30f;
        }
#pragma unroll
        for (int rh = 0; rh < 2; rh++) {
            float mt = -1e30f;
#pragma unroll
            for (int ni = 0; ni < 8; ni++)
                mt = fmaxf(mt, fmaxf(cs[ni][rh * 2], cs[ni][rh * 2 + 1]));
            mt = fmaxf(mt, __shfl_xor_sync(0xffffffffu, mt, 1));
            mt = fmaxf(mt, __shfl_xor_sync(0xffffffffu, mt, 2));
            float nm = fmaxf(m2[rh], mt);
            float al = __expf(m2[rh] - nm);
            float ps = 0.f;
#pragma unroll
            for (int ni = 0; ni < 8; ni++) {
                float p0 = __expf(cs[ni][rh * 2] - nm);
                float p1 = __expf(cs[ni][rh * 2 + 1] - nm);
                cs[ni][rh * 2] = p0; cs[ni][rh * 2 + 1] = p1;
                ps += p0 + p1;
            }
            ps += __shfl_xor_sync(0xffffffffu, ps, 1);
            ps += __shfl_xor_sync(0xffffffffu, ps, 2);
            l2[rh] = l2[rh] * al + ps;
            m2[rh] = nm;
#pragma unroll
            for (int ni = 0; ni < 16; ni++) {
                o[ni][rh * 2] *= al; o[ni][rh * 2 + 1] *= al;
            }
        }

        uint32_t avb = sb + (uint32_t)AV(st) * 2;
#pragma unroll
        for (int kchunk = 0; kchunk < 4; kchunk++) {
            int t0 = 2 * kchunk, t1 = 2 * kchunk + 1;
            uint32_t pa[4];
            pa[0] = pack2(__float2half_rn(cs[t0][0]), __float2half_rn(cs[t0][1]));
            pa[1] = pack2(__float2half_rn(cs[t0][2]), __float2half_rn(cs[t0][3]));
            pa[2] = pack2(__float2half_rn(cs[t1][0]), __float2half_rn(cs[t1][1]));
            pa[3] = pack2(__float2half_rn(cs[t1][2]), __float2half_rn(cs[t1][3]));
#pragma unroll
            for (int p = 0; p < 8; p++) {
                uint32_t kv = (uint32_t)(kchunk * 16 + ((lid >> 3) & 1) * 8 + (lid & 7));
                uint32_t d  = (uint32_t)(p * 16 + (((lid >> 4) & 1) << 3));
                uint32_t off = (kv * 136 + d) * 2;
                uint32_t bv4[4];
                ldmx4t(bv4, avb + off);
#pragma unroll
                for (int half = 0; half < 2; half++)
                    mma_f16(o[p * 2 + half], pa, &bv4[half * 2]);
            }
        }
    }

#pragma unroll
    for (int rh = 0; rh < 2; rh++) {
        float inv = 1.f / l2[rh];
        int row = q0 + wr + (lid >> 2) + rh * 8;
#pragma unroll
        for (int ni = 0; ni < 16; ni++) {
            int col = h * HD + ni * 8 + (lid & 3) * 2;
            size_t off = (size_t)(b * SQL + row) * DIM + col;
            *(uint32_t*)&co[off] = pack2(__float2half_rn(o[ni][rh * 2] * inv),
                                         __float2half_rn(o[ni][rh * 2 + 1] * inv));
        }
    }
}

// ---------------- launch ----------------
extern "C" void kernel_launch(void* const* d_in, const int* in_sizes, int n_in,
                              void* d_out, int out_size)
{
    const float* x   = (const float*)d_in[0];
    const float* pkv = (const float*)d_in[1];
    const float* skv = (const float*)d_in[2];
    const float* mkv = (const float*)d_in[3];
    const float* qm  = (const float*)d_in[4];
    const float* pm  = (const float*)d_in[5];
    const float* smk = (const float*)d_in[6];
    const float* mmk = (const float*)d_in[7];
    const float* rw  = (const float*)d_in[8];
    const float* Wq  = (const float*)d_in[9];
    const float* bq  = (const float*)d_in[10];
    const float* Wkp = (const float*)d_in[11];
    const float* bkp = (const float*)d_in[12];
    const float* Wvp = (const float*)d_in[13];
    const float* bvp = (const float*)d_in[14];
    const float* Wks = (const float*)d_in[15];
    const float* bks = (const float*)d_in[16];
    const float* Wvs = (const float*)d_in[17];
    const float* bvs = (const float*)d_in[18];
    const float* Wkm = (const float*)d_in[19];
    const float* bkm = (const float*)d_in[20];
    const float* Wvm = (const float*)d_in[21];
    const float* bvm = (const float*)d_in[22];
    const float* Wo  = (const float*)d_in[23];
    const float* bo  = (const float*)d_in[24];
    const float* lg  = (const float*)d_in[25];
    const float* lb  = (const float*)d_in[26];
    const float* W1  = (const float*)d_in[27];
    const float* W2  = (const float*)d_in[28];
    const float* ga  = (const float*)d_in[29];
    const float* gf  = (const float*)d_in[30];
    float* out = (float*)d_out;

    float* hb;
    cudaGetSymbolAddress((void**)&hb, g_h);

    fp16 *xn, *pk, *sk, *mk, *ct, *ln, *md, *qv, *k1, *v1;
    cudaGetSymbolAddress((void**)&xn, g_xn);
    cudaGetSymbolAddress((void**)&pk, g_pk);
    cudaGetSymbolAddress((void**)&sk, g_sk);
    cudaGetSymbolAddress((void**)&mk, g_mk);
    cudaGetSymbolAddress((void**)&ct, g_ct);
    cudaGetSymbolAddress((void**)&ln, g_ln);
    cudaGetSymbolAddress((void**)&md, g_md);
    cudaGetSymbolAddress((void**)&qv, g_q);
    cudaGetSymbolAddress((void**)&k1, g_k1);
    cudaGetSymbolAddress((void**)&v1, g_v1);

    fp16 *wq, *kp, *vp, *ks, *vs, *km, *vm, *wo, *w1, *w2;
    cudaGetSymbolAddress((void**)&wq, g_wq);
    cudaGetSymbolAddress((void**)&kp, g_kp); cudaGetSymbolAddress((void**)&vp, g_vp);
    cudaGetSymbolAddress((void**)&ks, g_ks); cudaGetSymbolAddress((void**)&vs, g_vs);
    cudaGetSymbolAddress((void**)&km, g_km); cudaGetSymbolAddress((void**)&vm, g_vm);
    cudaGetSymbolAddress((void**)&wo, g_wo);
    cudaGetSymbolAddress((void**)&w1, g_w1); cudaGetSymbolAddress((void**)&w2, g_w2);

    size_t gemm_sh = (size_t)NSTG * STGB;   // 150 KB
    cudaFuncSetAttribute(gemm_mma,  cudaFuncAttributeMaxDynamicSharedMemorySize, (int)gemm_sh);
    cudaFuncSetAttribute(gemm_proj, cudaFuncAttributeMaxDynamicSharedMemorySize, (int)gemm_sh);
    cudaFuncSetAttribute(attn_tc,   cudaFuncAttributeMaxDynamicSharedMemorySize, ATT_SMEM);

    // ---- prep (3 launches) ----
    rms_cvt_kernel<<<BN * SQL, 256>>>(x, rw, xn);

    int c0 = (BN * SP * DP) / 1024;
    int c1 = c0 + (BN * SS * DS) / 1024;
    int c2 = c1 + (BN * SMm * DMm) / 1024;
    cvt_all<<<c2, 256>>>(pkv, pk, c0, skv, sk, c1, mkv, mk, c2);

    WTab tab;
    {
        const float* Ws[10] = { Wq, Wkp, Wvp, Wks, Wvs, Wkm, Wvm, Wo, W1, W2 };
        fp16* Os[10]        = { wq, kp,  vp,  ks,  vs,  km,  vm,  wo, w1, w2 };
        int Kk[10] = { DIM, DP, DP, DS, DS, DMm, DMm, DIM, DIM, INNER };
        int Nn[10] = { DIM, DIM, DIM, DIM, DIM, DIM, DIM, DIM, INNER, DIM };
        int cum = 0;
        for (int i = 0; i < 10; i++) {
            tab.e[i].W = Ws[i]; tab.e[i].O = Os[i];
            tab.e[i].K = Kk[i]; tab.e[i].N = Nn[i];
            tab.e[i].cum = cum;
            cum += (Nn[i] / 32) * (Kk[i] / 32);
        }
        tcvt_all<<<cum, 256>>>(tab);
    }

    // ---- #4: ALL projections in one launch (M-tile 256) ----
    PTab pt;
    // seg0: Q (8 m-blocks x 16 n-blocks = 128)
    pt.e[0] = { xn, wq, wq, bq, bq, qv, qv, 0, 0, DIM, 16, 16, 8, 0, 0.25f };
    // seg1: protein K|V (my=4, nx=32, z=2 -> 256)
    pt.e[1] = { pk, kp, vp, bkp, bvp, k1, v1,
                (long)SP * DP, (long)SKV * DIM, DP, 32, 16, 4, 128, 1.f };
    // seg2: structure K|V (256)
    pt.e[2] = { sk, ks, vs, bks, bvs, k1 + (size_t)SP * DIM, v1 + (size_t)SP * DIM,
                (long)SS * DS, (long)SKV * DIM, DS, 32, 16, 4, 384, 1.f };
    // seg3: msa K|V (my=2, nx=32, z=2 -> 128)
    pt.e[3] = { mk, km, vm, bkm, bvm,
                k1 + (size_t)(SP + SS) * DIM, v1 + (size_t)(SP + SS) * DIM,
                (long)SMm * DMm, (long)SKV * DIM, DMm, 32, 16, 2, 640, 1.f };
    gemm_proj<<<768, 256, gemm_sh>>>(pt);

    // #5: flash attention -> fp16 ctx
    attn_tc<<<dim3(SQL / 128, NH, BN), 256, ATT_SMEM>>>(qv, k1, v1,
                                                        qm, pm, smk, mmk, ct);

    // #6: Wo projection + gated residual
    gemm_mma<<<dim3(DIM / 128, BN * SQL / 256, 1), 256, gemm_sh>>>(
        ct, wo, bo, x, ga, hb, nullptr, DIM, DIM, 1);

    // #7: LayerNorm -> fp16
    ln_cvt_kernel<<<BN * SQL, 256>>>(hb, lg, lb, ln);

    // #8: FFW up + GELU -> fp16
    gemm_mma<<<dim3(INNER / 128, BN * SQL / 256, 1), 256, gemm_sh>>>(
        ln, w1, nullptr, nullptr, nullptr, nullptr, md, INNER, DIM, 2);

    // #9: FFW down + gated residual -> out
    gemm_mma<<<dim3(DIM / 128, BN * SQL / 256, 1), 256, gemm_sh>>>(
        md, w2, nullptr, hb, gf, out, nullptr, DIM, INNER, 3);
}

// round 16
// speedup vs baseline: 1.1293x; 1.1293x over previous
#include <cuda_runtime.h>
#include <cuda_fp16.h>
#include <math.h>
#include <stdint.h>

// ---------------- problem constants ----------------
#define BN    2
#define SQL   1024
#define DIM   2048
#define NH    16
#define HD    128
#define SP    1024
#define SS    1024
#define SMm   512
#define SKV   2560
#define DP    1280
#define DS    1024
#define DMm   768
#define INNER 8192

typedef __half fp16;

// ---------------- scratch ----------------
__device__ __align__(256) float g_h  [BN*SQL*DIM];

__device__ __align__(256) fp16 g_xn [BN*SQL*DIM];
__device__ __align__(256) fp16 g_pk [BN*SP*DP];
__device__ __align__(256) fp16 g_sk [BN*SS*DS];
__device__ __align__(256) fp16 g_mk [BN*SMm*DMm];
__device__ __align__(256) fp16 g_ct [BN*SQL*DIM];
__device__ __align__(256) fp16 g_ln [BN*SQL*DIM];
__device__ __align__(256) fp16 g_md [BN*SQL*INNER];

__device__ __align__(256) fp16 g_q  [BN*SQL*DIM];
__device__ __align__(256) fp16 g_k1 [BN*SKV*DIM];
__device__ __align__(256) fp16 g_v1 [BN*SKV*DIM];

// fp16 weights in NATIVE [K][N] layout (no transpose)
__device__ __align__(256) fp16 g_wq [DIM*DIM];
__device__ __align__(256) fp16 g_kp [DP*DIM];
__device__ __align__(256) fp16 g_vp [DP*DIM];
__device__ __align__(256) fp16 g_ks [DS*DIM];
__device__ __align__(256) fp16 g_vs [DS*DIM];
__device__ __align__(256) fp16 g_km [DMm*DIM];
__device__ __align__(256) fp16 g_vm [DMm*DIM];
__device__ __align__(256) fp16 g_wo [DIM*DIM];
__device__ __align__(256) fp16 g_w1 [DIM*INNER];
__device__ __align__(256) fp16 g_w2 [INNER*DIM];

// ---------------- helpers ----------------
#define CP16(dst, src) asm volatile("cp.async.cg.shared.global [%0], [%1], 16;" :: "r"(dst), "l"(src))
#define CP4(dst, src)  asm volatile("cp.async.ca.shared.global [%0], [%1], 4;"  :: "r"(dst), "l"(src))
#define CP_COMMIT()  asm volatile("cp.async.commit_group;" ::: "memory")
#define CP_WAIT(n)   asm volatile("cp.async.wait_group %0;" :: "n"(n) : "memory")

__device__ __forceinline__ uint32_t smem_u32(const void* p) {
    uint32_t a;
    asm("{ .reg .u64 t; cvta.to.shared.u64 t, %1; cvt.u32.u64 %0, t; }" : "=r"(a) : "l"(p));
    return a;
}
__device__ __forceinline__ void mma_f16(float* c, const uint32_t* a, const uint32_t* b) {
    asm volatile("mma.sync.aligned.m16n8k16.row.col.f32.f16.f16.f32 "
        "{%0,%1,%2,%3}, {%4,%5,%6,%7}, {%8,%9}, {%0,%1,%2,%3};"
        : "+f"(c[0]), "+f"(c[1]), "+f"(c[2]), "+f"(c[3])
        : "r"(a[0]), "r"(a[1]), "r"(a[2]), "r"(a[3]), "r"(b[0]), "r"(b[1]));
}
__device__ __forceinline__ void ldmx4(uint32_t* r, uint32_t addr) {
    asm volatile("ldmatrix.sync.aligned.m8n8.x4.shared.b16 {%0,%1,%2,%3}, [%4];"
        : "=r"(r[0]), "=r"(r[1]), "=r"(r[2]), "=r"(r[3]) : "r"(addr));
}
__device__ __forceinline__ void ldmx4t(uint32_t* r, uint32_t addr) {
    asm volatile("ldmatrix.sync.aligned.m8n8.x4.trans.shared.b16 {%0,%1,%2,%3}, [%4];"
        : "=r"(r[0]), "=r"(r[1]), "=r"(r[2]), "=r"(r[3]) : "r"(addr));
}
__device__ __forceinline__ uint32_t pack2(fp16 a, fp16 b) {
    __half2 t(a, b);
    return *(uint32_t*)&t;
}

// ---------------- prep kernels ----------------
__global__ __launch_bounds__(256) void cvt_all(
    const float* __restrict__ x0, fp16* __restrict__ y0, int c0,
    const float* __restrict__ x1, fp16* __restrict__ y1, int c1,
    const float* __restrict__ x2, fp16* __restrict__ y2, int c2)
{
    int b = blockIdx.x;
    const float* x; fp16* y; int base;
    if (b < c0)      { x = x0; y = y0; base = b; }
    else if (b < c1) { x = x1; y = y1; base = b - c0; }
    else             { x = x2; y = y2; base = b - c1; }
    size_t i = ((size_t)base * 256 + threadIdx.x) * 4;
    float4 v = *(const float4*)(x + i);
    uint2 o;
    o.x = pack2(__float2half_rn(v.x), __float2half_rn(v.y));
    o.y = pack2(__float2half_rn(v.z), __float2half_rn(v.w));
    *(uint2*)(y + i) = o;
}

// merged weight convert (NO transpose): 4096 elems / block
struct CEnt { const float* W; fp16* O; int cum; };
struct CTab { CEnt e[10]; };

__global__ __launch_bounds__(256) void cvt_w(CTab tab) {
    int lin = blockIdx.x;
    int s = 0;
#pragma unroll
    for (int i = 1; i < 10; i++) if (lin >= tab.e[i].cum) s = i;
    const float* W = tab.e[s].W;
    fp16* O = tab.e[s].O;
    size_t base = (size_t)(lin - tab.e[s].cum) * 4096;
#pragma unroll
    for (int j = 0; j < 4; j++) {
        size_t i = base + j * 1024 + threadIdx.x * 4;
        float4 v = *(const float4*)(W + i);
        uint2 o;
        o.x = pack2(__float2half_rn(v.x), __float2half_rn(v.y));
        o.y = pack2(__float2half_rn(v.z), __float2half_rn(v.w));
        *(uint2*)(O + i) = o;
    }
}

__global__ __launch_bounds__(256) void rms_cvt_kernel(
    const float* __restrict__ x, const float* __restrict__ w, fp16* __restrict__ y) {
    __shared__ float red[256];
    int row = blockIdx.x;
    const float* xr = x + (size_t)row * DIM;
    float ss = 0.f;
    for (int c = threadIdx.x; c < DIM; c += 256) { float v = xr[c]; ss += v * v; }
    red[threadIdx.x] = ss; __syncthreads();
    for (int s = 128; s > 0; s >>= 1) {
        if (threadIdx.x < s) red[threadIdx.x] += red[threadIdx.x + s];
        __syncthreads();
    }
    float inv = rsqrtf(red[0] / (float)DIM + 1e-6f);
    for (int c = threadIdx.x; c < DIM; c += 256)
        y[(size_t)row * DIM + c] = __float2half_rn(xr[c] * inv * w[c]);
}

__global__ __launch_bounds__(256) void ln_cvt_kernel(
    const float* __restrict__ x, const float* __restrict__ g, const float* __restrict__ b,
    fp16* __restrict__ y) {
    __shared__ float r1[256], r2[256];
    int row = blockIdx.x;
    const float* xr = x + (size_t)row * DIM;
    float s1 = 0.f, s2 = 0.f;
    for (int c = threadIdx.x; c < DIM; c += 256) { float v = xr[c]; s1 += v; s2 += v * v; }
    r1[threadIdx.x] = s1; r2[threadIdx.x] = s2; __syncthreads();
    for (int s = 128; s > 0; s >>= 1) {
        if (threadIdx.x < s) { r1[threadIdx.x] += r1[threadIdx.x + s]; r2[threadIdx.x] += r2[threadIdx.x + s]; }
        __syncthreads();
    }
    float mu = r1[0] / (float)DIM;
    float rstd = rsqrtf(r2[0] / (float)DIM - mu * mu + 1e-5f);
    for (int c = threadIdx.x; c < DIM; c += 256)
        y[(size_t)row * DIM + c] = __float2half_rn((xr[c] - mu) * rstd * g[c] + b[c]);
}

// ---------------- shared GEMM mainloop (R14 geometry; B native [K][N]) ----------------
// Block tile 128x128, 8 warps (4m x 2n), warp tile 32x64, ktile 32, 4-stage.
// A smem: 128 rows x 40 (RS) fp16 = 10240 B. B smem: 32 k-rows x 136 (RSB) fp16 = 8704 B.
#define RS     40
#define RSB    136
#define A_STGB 10240
#define STGB   18944
#define NSTG   4

__device__ __forceinline__ void gemm_main(
    const fp16* __restrict__ Ab, const fp16* __restrict__ Bb, int K, int ldB,
    float c[2][8][4], char* dsm, int tid, int wm, int wn, int lid)
{
    uint32_t sbase = smem_u32(dsm);

    auto load_stage = [&](int k0, int st) {
        uint32_t base = sbase + (uint32_t)st * STGB;
        // A: 128 rows x 32 k = 512 cp16
#pragma unroll
        for (int j = 0; j < 2; j++) {
            int rem = tid + j * 256;
            int row = rem >> 2, ch = rem & 3;
            CP16(base + (uint32_t)(row * RS * 2 + ch * 16), Ab + (size_t)row * K + k0 + ch * 8);
        }
        // B: 32 k-rows x 128 n = 512 cp16 (coalesced 256B rows of W)
        uint32_t bb = base + A_STGB;
#pragma unroll
        for (int j = 0; j < 2; j++) {
            int rem = tid + j * 256;
            int row = rem >> 4, ch = rem & 15;
            CP16(bb + (uint32_t)(row * RSB * 2 + ch * 16), Bb + (size_t)(k0 + row) * ldB + ch * 8);
        }
    };

    const int nt = K >> 5;
    load_stage(0, 0);  CP_COMMIT();
    load_stage(32, 1); CP_COMMIT();
    load_stage(64, 2); CP_COMMIT();

    int st = 0;
    for (int t = 0; t < nt; t++) {
        int rem = nt - 1 - t;
        if (rem >= 2)      { CP_WAIT(2); }
        else if (rem == 1) { CP_WAIT(1); }
        else               { CP_WAIT(0); }
        __syncthreads();
        if (t + 3 < nt) {
            load_stage((t + 3) << 5, (st + 3) & 3);
            CP_COMMIT();
        }

        uint32_t A_b = sbase + (uint32_t)st * STGB;
        uint32_t B_b = A_b + A_STGB;

#pragma unroll
        for (int ks = 0; ks < 2; ks++) {
            int ko = ks * 16;
            uint32_t ah[2][4];
#pragma unroll
            for (int mi = 0; mi < 2; mi++) {
                uint32_t aoff = (uint32_t)((wm * 32 + mi * 16 + (lid & 15)) * RS + ko + ((lid >> 4) << 3)) * 2;
                ldmx4(ah[mi], A_b + aoff);
            }
            // B fragments via trans-ldmatrix from native [k][n] tile (attention-PV mapping)
            uint32_t krow = (uint32_t)(ko + ((lid >> 3) & 1) * 8 + (lid & 7));
#pragma unroll
            for (int pair = 0; pair < 4; pair++) {
                uint32_t ncol = (uint32_t)(wn * 64 + pair * 16 + (((lid >> 4) & 1) << 3));
                uint32_t b4[4];
                ldmx4t(b4, B_b + (krow * RSB + ncol) * 2);
#pragma unroll
                for (int mi = 0; mi < 2; mi++) {
                    mma_f16(c[mi][pair * 2 + 0], ah[mi], &b4[0]);
                    mma_f16(c[mi][pair * 2 + 1], ah[mi], &b4[2]);
                }
            }
        }
        st = (st + 1) & 3;
    }
}

// ---------------- merged projection GEMM ----------------
struct PSeg {
    const fp16* A; const fp16* Bk; const fp16* Bv;
    const float* bk; const float* bv;
    fp16* Ok; fp16* Ov;
    long aStride, cStride;
    int Kdim, nx, nxK, my, cum;
    float scale;
};
struct PTab { PSeg e[4]; };

__global__ __launch_bounds__(256) void gemm_proj(PTab tab) {
    extern __shared__ __align__(128) char dsm[];
    int tid = threadIdx.x, wid = tid >> 5, lid = tid & 31;
    int wm = wid & 3, wn = wid >> 2;

    int bid = blockIdx.x;
    int s = 0;
#pragma unroll
    for (int i = 1; i < 4; i++) if (bid >= tab.e[i].cum) s = i;
    PSeg sg = tab.e[s];
    int local = bid - sg.cum;
    int per = sg.nx * sg.my;
    int z = local / per;
    int rem2 = local - z * per;
    int mb = rem2 / sg.nx;
    int nbk = rem2 - mb * sg.nx;
    int m0 = mb << 7, n0 = nbk << 7;

    const fp16* B; const float* bias; fp16* O;
    if (nbk < sg.nxK) { B = sg.Bk; bias = sg.bk; O = sg.Ok; }
    else { B = sg.Bv; bias = sg.bv; O = sg.Ov; n0 -= sg.nxK << 7; }

    const fp16* A = sg.A + (size_t)z * sg.aStride + (size_t)m0 * sg.Kdim;
    B += n0;                                  // column offset into [K][DIM]
    O += (size_t)z * sg.cStride;
    float scale = sg.scale;

    float c[2][8][4];
#pragma unroll
    for (int mi = 0; mi < 2; mi++)
#pragma unroll
        for (int ni = 0; ni < 8; ni++)
#pragma unroll
            for (int r = 0; r < 4; r++) c[mi][ni][r] = 0.f;

    gemm_main(A, B, sg.Kdim, DIM, c, dsm, tid, wm, wn, lid);

#pragma unroll
    for (int mi = 0; mi < 2; mi++) {
#pragma unroll
        for (int ni = 0; ni < 8; ni++) {
            int col = n0 + wn * 64 + ni * 8 + (lid & 3) * 2;
            float bcol0 = bias[col], bcol1 = bias[col + 1];
#pragma unroll
            for (int rh = 0; rh < 2; rh++) {
                int m = m0 + wm * 32 + mi * 16 + (lid >> 2) + rh * 8;
                float v0 = c[mi][ni][rh * 2 + 0];
                float v1 = c[mi][ni][rh * 2 + 1];
                size_t o = (size_t)m * DIM + col;
                *(uint32_t*)&O[o] = pack2(__float2half_rn((v0 + bcol0) * scale),
                                          __float2half_rn((v1 + bcol1) * scale));
            }
        }
    }
}

// ---------------- general GEMM ----------------
// epi: 1: C=res+tanh(g)*(acc+bias) | 2: gelu->fp16 | 3: C=res+tanh(g)*acc
__global__ __launch_bounds__(256) void gemm_mma(
    const fp16* __restrict__ A,
    const fp16* __restrict__ B,
    const float* __restrict__ bias,
    const float* __restrict__ res, const float* __restrict__ gate,
    float* __restrict__ C, fp16* __restrict__ O,
    int N, int K, int epi)
{
    extern __shared__ __align__(128) char dsm[];

    int tid = threadIdx.x, wid = tid >> 5, lid = tid & 31;
    int wm = wid & 3, wn = wid >> 2;
    int m0 = blockIdx.y << 7, n0 = blockIdx.x << 7;

    float c[2][8][4];
#pragma unroll
    for (int mi = 0; mi < 2; mi++)
#pragma unroll
        for (int ni = 0; ni < 8; ni++)
#pragma unroll
            for (int r = 0; r < 4; r++) c[mi][ni][r] = 0.f;

    gemm_main(A + (size_t)m0 * K, B + n0, K, N, c, dsm, tid, wm, wn, lid);

    float gv = (epi == 1 || epi == 3) ? tanhf(*gate) : 0.f;
#pragma unroll
    for (int mi = 0; mi < 2; mi++) {
#pragma unroll
        for (int ni = 0; ni < 8; ni++) {
            int col = n0 + wn * 64 + ni * 8 + (lid & 3) * 2;
            float bcol0 = 0.f, bcol1 = 0.f;
            if (epi == 1) { bcol0 = bias[col]; bcol1 = bias[col + 1]; }
#pragma unroll
            for (int rh = 0; rh < 2; rh++) {
                int m = m0 + wm * 32 + mi * 16 + (lid >> 2) + rh * 8;
                float v0 = c[mi][ni][rh * 2 + 0];
                float v1 = c[mi][ni][rh * 2 + 1];
                size_t o = (size_t)m * N + col;
                if (epi == 1) {
                    C[o]     = res[o]     + gv * (v0 + bcol0);
                    C[o + 1] = res[o + 1] + gv * (v1 + bcol1);
                } else if (epi == 2) {
                    float g0 = 0.5f * v0 * (1.f + erff(v0 * 0.70710678118654752f));
                    float g1 = 0.5f * v1 * (1.f + erff(v1 * 0.70710678118654752f));
                    *(uint32_t*)&O[o] = pack2(__float2half_rn(g0), __float2half_rn(g1));
                } else { // epi == 3
                    C[o]     = res[o]     + gv * v0;
                    C[o + 1] = res[o + 1] + gv * v1;
                }
            }
        }
    }
}

// ---------------- tensor-core flash attention (fp16, unchanged) ----------------
#define AQ 0
#define AK(st) (17408 + (st) * 8704)
#define AV(st) (34816 + (st) * 8704)
#define AMSK_BYTES 104448
#define ATT_SMEM (AMSK_BYTES + 512)
#define NKT (SKV / 64)

__global__ __launch_bounds__(256) void attn_tc(
    const fp16* __restrict__ qv, const fp16* __restrict__ kk, const fp16* __restrict__ vv,
    const float* __restrict__ qmask, const float* __restrict__ pmask,
    const float* __restrict__ smask, const float* __restrict__ mmask,
    fp16* __restrict__ co)
{
    extern __shared__ __align__(128) char dsm[];
    uint32_t sb = smem_u32(dsm);

    int b = blockIdx.z, h = blockIdx.y, q0 = blockIdx.x * 128;
    int tid = threadIdx.x, wid = tid >> 5, lid = tid & 31;
    int wr = wid * 16;

#pragma unroll
    for (int j = 0; j < 8; j++) {
        int rem = tid + j * 256;
        int r = rem >> 4, cch = rem & 15;
        CP16(sb + (uint32_t)(AQ + r * 136 + cch * 8) * 2,
             qv + (size_t)(b * SQL + q0 + r) * DIM + h * HD + cch * 8);
    }

    auto load_stage = [&](int kt, int st) {
#pragma unroll
        for (int grp = 0; grp < 2; grp++) {
            const fp16* base = grp ? vv : kk;
            uint32_t ab = grp ? (uint32_t)AV(st) : (uint32_t)AK(st);
#pragma unroll
            for (int j = 0; j < 4; j++) {
                int rem = tid + j * 256;
                int r = rem >> 4, cch = rem & 15;
                CP16(sb + (ab + (uint32_t)(r * 136 + cch * 8)) * 2,
                     base + (size_t)(b * SKV + kt + r) * DIM + h * HD + cch * 8);
            }
        }
        if (tid < 64) {
            int kidx = kt + tid;
            const float* srcm;
            if (kidx < SP)           srcm = pmask + b * SP + kidx;
            else if (kidx < SP + SS) srcm = smask + b * SS + (kidx - SP);
            else                     srcm = mmask + b * SMm + (kidx - SP - SS);
            CP4(sb + AMSK_BYTES + st * 256 + tid * 4, srcm);
        }
    };

    float qm2[2];
    qm2[0] = qmask[b * SQL + q0 + wr + (lid >> 2)];
    qm2[1] = qmask[b * SQL + q0 + wr + (lid >> 2) + 8];

    float m2[2] = { -1e30f, -1e30f }, l2[2] = { 0.f, 0.f };
    float o[16][4];
#pragma unroll
    for (int ni = 0; ni < 16; ni++)
#pragma unroll
        for (int r = 0; r < 4; r++) o[ni][r] = 0.f;

    load_stage(0, 0);
    CP_COMMIT();

    for (int t = 0; t < NKT; t++) {
        int st = t & 1;
        CP_WAIT(0);
        __syncthreads();
        if (t + 1 < NKT) { load_stage((t + 1) * 64, st ^ 1); CP_COMMIT(); }

        float cs[8][4];
#pragma unroll
        for (int ni = 0; ni < 8; ni++)
#pragma unroll
            for (int r = 0; r < 4; r++) cs[ni][r] = 0.f;

        uint32_t akb = sb + (uint32_t)AK(st) * 2;
#pragma unroll
        for (int ko = 0; ko < 8; ko++) {
            uint32_t aoff = (uint32_t)((wr + (lid & 15)) * 136 + ko * 16 + ((lid >> 4) << 3)) * 2;
            uint32_t aq[4];
            ldmx4(aq, sb + AQ * 2 + aoff);
#pragma unroll
            for (int p = 0; p < 4; p++) {
                uint32_t brow = (uint32_t)(p * 16 + (lid & 7) + ((lid >> 4) << 3));
                uint32_t boff = (brow * 136 + ko * 16 + (((lid >> 3) & 1) << 3)) * 2;
                uint32_t b4[4];
                ldmx4(b4, akb + boff);
#pragma unroll
                for (int half = 0; half < 2; half++)
                    mma_f16(cs[p * 2 + half], aq, &b4[half * 2]);
            }
        }

        const float* kmf = (const float*)(dsm + AMSK_BYTES + st * 256);
#pragma unroll
        for (int ni = 0; ni < 8; ni++) {
            int c0 = ni * 8 + (lid & 3) * 2;
            float km0 = kmf[c0], km1 = kmf[c0 + 1];
            if (qm2[0] == 0.f || km0 == 0.f) cs[ni][0] = -1e30f;
            if (qm2[0] == 0.f || km1 == 0.f) cs[ni][1] = -1e30f;
            if (qm2[1] == 0.f || km0 == 0.f) cs[ni][2] = -1e30f;
            if (qm2[1] == 0.f || km1 == 0.f) cs[ni][3] = -1e30f;
        }
#pragma unroll
        for (int rh = 0; rh < 2; rh++) {
            float mt = -1e30f;
#pragma unroll
            for (int ni = 0; ni < 8; ni++)
                mt = fmaxf(mt, fmaxf(cs[ni][rh * 2], cs[ni][rh * 2 + 1]));
            mt = fmaxf(mt, __shfl_xor_sync(0xffffffffu, mt, 1));
            mt = fmaxf(mt, __shfl_xor_sync(0xffffffffu, mt, 2));
            float nm = fmaxf(m2[rh], mt);
            float al = __expf(m2[rh] - nm);
            float ps = 0.f;
#pragma unroll
            for (int ni = 0; ni < 8; ni++) {
                float p0 = __expf(cs[ni][rh * 2] - nm);
                float p1 = __expf(cs[ni][rh * 2 + 1] - nm);
                cs[ni][rh * 2] = p0; cs[ni][rh * 2 + 1] = p1;
                ps += p0 + p1;
            }
            ps += __shfl_xor_sync(0xffffffffu, ps, 1);
            ps += __shfl_xor_sync(0xffffffffu, ps, 2);
            l2[rh] = l2[rh] * al + ps;
            m2[rh] = nm;
#pragma unroll
            for (int ni = 0; ni < 16; ni++) {
                o[ni][rh * 2] *= al; o[ni][rh * 2 + 1] *= al;
            }
        }

        uint32_t avb = sb + (uint32_t)AV(st) * 2;
#pragma unroll
        for (int kchunk = 0; kchunk < 4; kchunk++) {
            int t0 = 2 * kchunk, t1 = 2 * kchunk + 1;
            uint32_t pa[4];
            pa[0] = pack2(__float2half_rn(cs[t0][0]), __float2half_rn(cs[t0][1]));
            pa[1] = pack2(__float2half_rn(cs[t0][2]), __float2half_rn(cs[t0][3]));
            pa[2] = pack2(__float2half_rn(cs[t1][0]), __float2half_rn(cs[t1][1]));
            pa[3] = pack2(__float2half_rn(cs[t1][2]), __float2half_rn(cs[t1][3]));
#pragma unroll
            for (int p = 0; p < 8; p++) {
                uint32_t kv = (uint32_t)(kchunk * 16 + ((lid >> 3) & 1) * 8 + (lid & 7));
                uint32_t d  = (uint32_t)(p * 16 + (((lid >> 4) & 1) << 3));
                uint32_t off = (kv * 136 + d) * 2;
                uint32_t bv4[4];
                ldmx4t(bv4, avb + off);
#pragma unroll
                for (int half = 0; half < 2; half++)
                    mma_f16(o[p * 2 + half], pa, &bv4[half * 2]);
            }
        }
    }

#pragma unroll
    for (int rh = 0; rh < 2; rh++) {
        float inv = 1.f / l2[rh];
        int row = q0 + wr + (lid >> 2) + rh * 8;
#pragma unroll
        for (int ni = 0; ni < 16; ni++) {
            int col = h * HD + ni * 8 + (lid & 3) * 2;
            size_t off = (size_t)(b * SQL + row) * DIM + col;
            *(uint32_t*)&co[off] = pack2(__float2half_rn(o[ni][rh * 2] * inv),
                                         __float2half_rn(o[ni][rh * 2 + 1] * inv));
        }
    }
}

// ---------------- launch ----------------
extern "C" void kernel_launch(void* const* d_in, const int* in_sizes, int n_in,
                              void* d_out, int out_size)
{
    const float* x   = (const float*)d_in[0];
    const float* pkv = (const float*)d_in[1];
    const float* skv = (const float*)d_in[2];
    const float* mkv = (const float*)d_in[3];
    const float* qm  = (const float*)d_in[4];
    const float* pm  = (const float*)d_in[5];
    const float* smk = (const float*)d_in[6];
    const float* mmk = (const float*)d_in[7];
    const float* rw  = (const float*)d_in[8];
    const float* Wq  = (const float*)d_in[9];
    const float* bq  = (const float*)d_in[10];
    const float* Wkp = (const float*)d_in[11];
    const float* bkp = (const float*)d_in[12];
    const float* Wvp = (const float*)d_in[13];
    const float* bvp = (const float*)d_in[14];
    const float* Wks = (const float*)d_in[15];
    const float* bks = (const float*)d_in[16];
    const float* Wvs = (const float*)d_in[17];
    const float* bvs = (const float*)d_in[18];
    const float* Wkm = (const float*)d_in[19];
    const float* bkm = (const float*)d_in[20];
    const float* Wvm = (const float*)d_in[21];
    const float* bvm = (const float*)d_in[22];
    const float* Wo  = (const float*)d_in[23];
    const float* bo  = (const float*)d_in[24];
    const float* lg  = (const float*)d_in[25];
    const float* lb  = (const float*)d_in[26];
    const float* W1  = (const float*)d_in[27];
    const float* W2  = (const float*)d_in[28];
    const float* ga  = (const float*)d_in[29];
    const float* gf  = (const float*)d_in[30];
    float* out = (float*)d_out;

    float* hb;
    cudaGetSymbolAddress((void**)&hb, g_h);

    fp16 *xn, *pk, *sk, *mk, *ct, *ln, *md, *qv, *k1, *v1;
    cudaGetSymbolAddress((void**)&xn, g_xn);
    cudaGetSymbolAddress((void**)&pk, g_pk);
    cudaGetSymbolAddress((void**)&sk, g_sk);
    cudaGetSymbolAddress((void**)&mk, g_mk);
    cudaGetSymbolAddress((void**)&ct, g_ct);
    cudaGetSymbolAddress((void**)&ln, g_ln);
    cudaGetSymbolAddress((void**)&md, g_md);
    cudaGetSymbolAddress((void**)&qv, g_q);
    cudaGetSymbolAddress((void**)&k1, g_k1);
    cudaGetSymbolAddress((void**)&v1, g_v1);

    fp16 *wq, *kp, *vp, *ks, *vs, *km, *vm, *wo, *w1, *w2;
    cudaGetSymbolAddress((void**)&wq, g_wq);
    cudaGetSymbolAddress((void**)&kp, g_kp); cudaGetSymbolAddress((void**)&vp, g_vp);
    cudaGetSymbolAddress((void**)&ks, g_ks); cudaGetSymbolAddress((void**)&vs, g_vs);
    cudaGetSymbolAddress((void**)&km, g_km); cudaGetSymbolAddress((void**)&vm, g_vm);
    cudaGetSymbolAddress((void**)&wo, g_wo);
    cudaGetSymbolAddress((void**)&w1, g_w1); cudaGetSymbolAddress((void**)&w2, g_w2);

    size_t gemm_sh = (size_t)NSTG * STGB;   // ~74 KB
    cudaFuncSetAttribute(gemm_mma,  cudaFuncAttributeMaxDynamicSharedMemorySize, (int)gemm_sh);
    cudaFuncSetAttribute(gemm_proj, cudaFuncAttributeMaxDynamicSharedMemorySize, (int)gemm_sh);
    cudaFuncSetAttribute(attn_tc,   cudaFuncAttributeMaxDynamicSharedMemorySize, ATT_SMEM);

    // ---- prep (3 launches) ----
    rms_cvt_kernel<<<BN * SQL, 256>>>(x, rw, xn);

    int c0 = (BN * SP * DP) / 1024;
    int c1 = c0 + (BN * SS * DS) / 1024;
    int c2 = c1 + (BN * SMm * DMm) / 1024;
    cvt_all<<<c2, 256>>>(pkv, pk, c0, skv, sk, c1, mkv, mk, c2);

    CTab ct_tab;
    {
        const float* Ws[10] = { Wq, Wkp, Wvp, Wks, Wvs, Wkm, Wvm, Wo, W1, W2 };
        fp16* Os[10]        = { wq, kp,  vp,  ks,  vs,  km,  vm,  wo, w1, w2 };
        long sz[10] = { (long)DIM*DIM, (long)DP*DIM, (long)DP*DIM, (long)DS*DIM, (long)DS*DIM,
                        (long)DMm*DIM, (long)DMm*DIM, (long)DIM*DIM, (long)DIM*INNER, (long)INNER*DIM };
        int cum = 0;
        for (int i = 0; i < 10; i++) {
            ct_tab.e[i].W = Ws[i]; ct_tab.e[i].O = Os[i]; ct_tab.e[i].cum = cum;
            cum += (int)(sz[i] / 4096);
        }
        cvt_w<<<cum, 256>>>(ct_tab);
    }

    // ---- #4: ALL projections in one launch (R14 geometry) ----
    PTab pt;
    pt.e[0] = { xn, wq, wq, bq, bq, qv, qv, 0, 0, DIM, 16, 16, 16, 0, 0.25f };
    pt.e[1] = { pk, kp, vp, bkp, bvp, k1, v1,
                (long)SP * DP, (long)SKV * DIM, DP, 32, 16, 8, 256, 1.f };
    pt.e[2] = { sk, ks, vs, bks, bvs, k1 + (size_t)SP * DIM, v1 + (size_t)SP * DIM,
                (long)SS * DS, (long)SKV * DIM, DS, 32, 16, 8, 768, 1.f };
    pt.e[3] = { mk, km, vm, bkm, bvm,
                k1 + (size_t)(SP + SS) * DIM, v1 + (size_t)(SP + SS) * DIM,
                (long)SMm * DMm, (long)SKV * DIM, DMm, 32, 16, 4, 1280, 1.f };
    gemm_proj<<<1536, 256, gemm_sh>>>(pt);

    // #5: flash attention -> fp16 ctx
    attn_tc<<<dim3(SQL / 128, NH, BN), 256, ATT_SMEM>>>(qv, k1, v1,
                                                        qm, pm, smk, mmk, ct);

    // #6: Wo projection + gated residual
    gemm_mma<<<dim3(DIM / 128, 16, 1), 256, gemm_sh>>>(
        ct, wo, bo, x, ga, hb, nullptr, DIM, DIM, 1);

    // #7: LayerNorm -> fp16
    ln_cvt_kernel<<<BN * SQL, 256>>>(hb, lg, lb, ln);

    // #8: FFW up + GELU -> fp16
    gemm_mma<<<dim3(INNER / 128, 16, 1), 256, gemm_sh>>>(
        ln, w1, nullptr, nullptr, nullptr, nullptr, md, INNER, DIM, 2);

    // #9: FFW down + gated residual -> out
    gemm_mma<<<dim3(DIM / 128, 16, 1), 256, gemm_sh>>>(
        md, w2, nullptr, hb, gf, out, nullptr, DIM, INNER, 3);
}